// round 9
// baseline (speedup 1.0000x reference)
#include <cuda_runtime.h>
#include <cuda.h>
#include <cuda_bf16.h>

#define B_    64
#define L_    16384
#define D_    64
#define KSEL  256
#define TILE  128
#define NT    4
#define ROWW  68
#define CAP   2048
#define TILE_BYTES (TILE * D_ * 4)   // 32768
#define SIM_THR 2.10f                // conservative collect threshold

__device__ float g_sim[B_ * L_];
__device__ int g_cnt[B_];                        // zero-init; B re-zeroes
__device__ unsigned long long g_cand[B_ * CAP];

__device__ __forceinline__ unsigned f2u(float f) {
    unsigned b = __float_as_uint(f);
    return (b & 0x80000000u) ? ~b : (b | 0x80000000u);
}
__device__ __forceinline__ float u2f(unsigned u) {
    unsigned b = (u & 0x80000000u) ? (u & 0x7FFFFFFFu) : ~u;
    return __uint_as_float(b);
}

// ---- mbarrier / TMA helpers -----------------------------------------------
__device__ __forceinline__ unsigned sm_u32(const void* p) {
    return (unsigned)__cvta_generic_to_shared(p);
}
__device__ __forceinline__ void mbar_init(void* m, unsigned cnt) {
    asm volatile("mbarrier.init.shared.b64 [%0], %1;"
                 :: "r"(sm_u32(m)), "r"(cnt) : "memory");
}
__device__ __forceinline__ void mbar_expect_tx(void* m, unsigned bytes) {
    asm volatile("mbarrier.arrive.expect_tx.shared.b64 _, [%0], %1;"
                 :: "r"(sm_u32(m)), "r"(bytes) : "memory");
}
__device__ __forceinline__ void tma_load3d(void* dst, const CUtensorMap* tm,
                                           int x, int y, int z, void* m) {
    asm volatile(
        "cp.async.bulk.tensor.3d.shared::cta.global.tile.mbarrier::complete_tx::bytes "
        "[%0], [%1, {%2, %3, %4}], [%5];"
        :: "r"(sm_u32(dst)), "l"(tm), "r"(x), "r"(y), "r"(z), "r"(sm_u32(m))
        : "memory");
}
__device__ __forceinline__ void mbar_wait(void* m, unsigned parity) {
    asm volatile(
        "{\n\t.reg .pred P;\n\t"
        "W%=:\n\t"
        "mbarrier.try_wait.parity.acquire.cta.shared::cta.b64 P, [%0], %1, 0x989680;\n\t"
        "@P bra D%=;\n\t"
        "bra W%=;\n\t"
        "D%=:\n\t}"
        :: "r"(sm_u32(m)), "r"(parity) : "memory");
}

// Warp-aggregated candidate append (one ATOMG per warp with any candidate).
__device__ __forceinline__ void append_cand(int b, bool take, unsigned u, int i,
                                            int lane) {
    unsigned m = __ballot_sync(0xFFFFFFFFu, take);
    if (m) {
        int leader = __ffs(m) - 1;
        int basepos = 0;
        if (lane == leader)
            basepos = atomicAdd(&g_cnt[b], __popc(m));
        basepos = __shfl_sync(0xFFFFFFFFu, basepos, leader);
        if (take) {
            int p = basepos + __popc(m & ((1u << lane) - 1));
            if (p < CAP)
                g_cand[b * CAP + p] =
                    ((unsigned long long)u << 32) | (unsigned)(~i);
        }
    }
}

// ---------------------------------------------------------------------------
// Kernel A (TMA + SW128): sims + fused threshold collect. FP tree identical
// to the proven R8 kernel (swizzle changes addresses only, c order 0..15).
// ---------------------------------------------------------------------------
__global__ void __launch_bounds__(TILE) sim_tma_kernel(
    const __grid_constant__ CUtensorMap tmap,
    const float* __restrict__ q,
    const float* __restrict__ gp)
{
    extern __shared__ __align__(1024) float smem[];
    float4* qsm = reinterpret_cast<float4*>(smem + 2 * TILE * D_);
    unsigned long long* mbar =
        reinterpret_cast<unsigned long long*>(smem + 2 * TILE * D_ + 64);

    const int b    = blockIdx.y;
    const int t0   = blockIdx.x * (TILE * NT);
    const int tid  = threadIdx.x;
    const int lane = tid & 31;
    const unsigned uthr = f2u(SIM_THR);

    if (tid < D_ / 4)
        qsm[tid] = reinterpret_cast<const float4*>(q + b * D_)[tid];
    if (tid == 0) { mbar_init(&mbar[0], 1); mbar_init(&mbar[1], 1); }
    __syncthreads();

    if (tid == 0) {
        mbar_expect_tx(&mbar[0], TILE_BYTES);
        tma_load3d(smem, &tmap, 0, 2 * t0, b, &mbar[0]);
    }

    float qq = 0.f;
#pragma unroll
    for (int i = 0; i < D_ / 4; i++) {
        float4 t = qsm[i];
        qq += t.x * t.x + t.y * t.y + t.z * t.z + t.w * t.w;
    }
    const float rq = gp[0] * rsqrtf(qq);

#pragma unroll
    for (int t = 0; t < NT; t++) {
        if (t + 1 < NT && tid == 0) {
            int nb = (t + 1) & 1;
            mbar_expect_tx(&mbar[nb], TILE_BYTES);
            tma_load3d(smem + nb * (TILE * D_), &tmap,
                       0, 2 * (t0 + (t + 1) * TILE), b, &mbar[nb]);
        }
        mbar_wait(&mbar[t & 1], (t >> 1) & 1);

        const float* base = smem + (t & 1) * (TILE * D_);
        float dot = 0.f, kk = 0.f;
#pragma unroll
        for (int i = 0; i < 16; i++) {
            int r   = 2 * tid + (i >> 3);
            int c16 = (i & 7) ^ (r & 7);
            float4 kv = *reinterpret_cast<const float4*>(base + r * 32 + c16 * 4);
            float4 qv = qsm[i];
            dot += qv.x * kv.x + qv.y * kv.y + qv.z * kv.z + qv.w * kv.w;
            kk  += kv.x * kv.x + kv.y * kv.y + kv.z * kv.z + kv.w * kv.w;
        }
        float sim = dot * rq * rsqrtf(kk);
        int gi = t0 + t * TILE + tid;
        g_sim[b * L_ + gi] = sim;
        unsigned u = f2u(sim);
        append_cand(b, u >= uthr, u, gi, lane);

        __syncthreads();   // buffer free before reuse at t+2
    }
}

// ---------------------------------------------------------------------------
// Kernel A fallback (cp.async) — if tensormap encode unavailable.
// ---------------------------------------------------------------------------
__global__ void __launch_bounds__(TILE) sim_kernel(
    const float* __restrict__ q,
    const float* __restrict__ keys,
    const float* __restrict__ gp)
{
    extern __shared__ __align__(16) float tile[];
    __shared__ __align__(16) float4 qsm[D_ / 4];

    const int b    = blockIdx.y;
    const int t0   = blockIdx.x * (TILE * NT);
    const int tid  = threadIdx.x;
    const int lane = tid & 31;
    const unsigned uthr = f2u(SIM_THR);

    if (tid < D_ / 4)
        qsm[tid] = reinterpret_cast<const float4*>(q + b * D_)[tid];

    const float4* kbase = reinterpret_cast<const float4*>(
        keys + (size_t)b * L_ * D_ + (size_t)t0 * D_);

    auto issue = [&](int tt, int buf) {
        const float4* src = kbase + tt * (TILE * 16);
        float* dstbase = tile + buf * (TILE * ROWW);
#pragma unroll
        for (int j = 0; j < 16; j++) {
            int f = j * TILE + tid;
            int l = f >> 4;
            int c = f & 15;
            unsigned dst = sm_u32(&dstbase[l * ROWW + c * 4]);
            asm volatile("cp.async.cg.shared.global [%0], [%1], 16;\n"
                         :: "r"(dst), "l"(src + f));
        }
        asm volatile("cp.async.commit_group;\n");
    };

    issue(0, 0);
    __syncthreads();
    float qq = 0.f;
#pragma unroll
    for (int i = 0; i < D_ / 4; i++) {
        float4 t = qsm[i];
        qq += t.x * t.x + t.y * t.y + t.z * t.z + t.w * t.w;
    }
    const float rq = gp[0] * rsqrtf(qq);

#pragma unroll
    for (int t = 0; t < NT; t++) {
        if (t + 1 < NT) {
            issue(t + 1, (t + 1) & 1);
            asm volatile("cp.async.wait_group 1;\n");
        } else {
            asm volatile("cp.async.wait_group 0;\n");
        }
        __syncthreads();
        const float* tb = tile + (t & 1) * (TILE * ROWW);
        float dot = 0.f, kk = 0.f;
#pragma unroll
        for (int i = 0; i < 16; i++) {
            float4 kv = *reinterpret_cast<const float4*>(&tb[tid * ROWW + i * 4]);
            float4 qv = qsm[i];
            dot += qv.x * kv.x + qv.y * kv.y + qv.z * kv.z + qv.w * kv.w;
            kk  += kv.x * kv.x + kv.y * kv.y + kv.z * kv.z + kv.w * kv.w;
        }
        float sim = dot * rq * rsqrtf(kk);
        int gi = t0 + t * TILE + tid;
        g_sim[b * L_ + gi] = sim;
        unsigned u = f2u(sim);
        append_cand(b, u >= uthr, u, gi, lane);
        __syncthreads();
    }
}

// ---------------------------------------------------------------------------
// Kernel B: rank pre-collected candidates + softmax + gather. One CTA/batch.
// Fallback (never taken for valid threshold): exact radix-select over g_sim.
// ---------------------------------------------------------------------------
__global__ void __launch_bounds__(1024) topk_kernel(
    const float* __restrict__ values,
    float* __restrict__ out)
{
    __shared__ __align__(16) unsigned long long cand[CAP];
    __shared__ int s_rank[CAP];
    __shared__ unsigned long long s_key[KSEL];
    __shared__ float s_e[KSEL];
    __shared__ float s_sum;
    __shared__ unsigned s_cnt;

    const int b   = blockIdx.x;
    const int tid = threadIdx.x;
    const int T   = 1024;

    int n = g_cnt[b];
    bool ok = (n >= KSEL && n <= CAP - 2);

    if (ok) {
        for (int i = tid; i < n; i += T)
            cand[i] = g_cand[b * CAP + i];
    } else {
        // exact fallback: radix-select the 256th-largest u over g_sim
        const float* simrow = g_sim + b * L_;
        unsigned prefix = 0;
        for (int bit = 31; bit >= 0; bit--) {
            unsigned thr = prefix | (1u << bit);
            if (tid == 0) s_cnt = 0;
            __syncthreads();
            unsigned c = 0;
            for (int i = tid; i < L_; i += T)
                c += (f2u(simrow[i]) >= thr);
            if (c) atomicAdd(&s_cnt, c);
            __syncthreads();
            if (s_cnt >= KSEL) prefix = thr;
            __syncthreads();
        }
        if (tid == 0) s_cnt = 0;
        __syncthreads();
        for (int i = tid; i < L_; i += T) {
            unsigned u = f2u(simrow[i]);
            if (u >= prefix) {
                int p = atomicAdd(&s_cnt, 1);
                if (p < CAP - 2)
                    cand[p] = ((unsigned long long)u << 32) | (unsigned)(~i);
            }
        }
        __syncthreads();
        n = (int)s_cnt;
        if (n > CAP - 2) n = CAP - 2;
    }
    __syncthreads();
    if (tid == 0) {
        g_cnt[b] = 0;                 // reset for next replay
        cand[n] = 0ull; cand[n + 1] = 0ull;   // pad for pair loads
    }
    for (int i = tid; i < n; i += T) s_rank[i] = 0;
    __syncthreads();

    // exact rank (desc value, asc index): quarter-split pairwise count
    {
        const int npairs = (n + 1) >> 1;
        const int npq    = (npairs + 3) >> 2;
        const int quart  = tid >> 8;
        const int i0     = tid & 255;
        const int jp0    = quart * npq;
        const int jp1    = (jp0 + npq < npairs) ? jp0 + npq : npairs;
        const ulonglong2* cp = reinterpret_cast<const ulonglong2*>(cand);

        for (int i = i0; i < n; i += 256) {
            unsigned long long me = cand[i];
            int r = 0;
            for (int jp = jp0; jp < jp1; jp++) {
                ulonglong2 p = cp[jp];
                r += (p.x > me) + (p.y > me);
            }
            if (r) atomicAdd(&s_rank[i], r);
        }
    }
    __syncthreads();

    for (int i = tid; i < n; i += T) {
        int r = s_rank[i];
        if (r < KSEL) s_key[r] = cand[i];
    }
    __syncthreads();

    // softmax over top-256 + gather + output
    float maxs = u2f((unsigned)(s_key[0] >> 32));
    float e = 0.f;
    if (tid < KSEL) {
        e = expf(u2f((unsigned)(s_key[tid] >> 32)) - maxs);
        s_e[tid] = e;
    }
    __syncthreads();
    if (tid < 32) {
        float acc = 0.f;
#pragma unroll
        for (int j = 0; j < KSEL / 32; j++) acc += s_e[tid + j * 32];
#pragma unroll
        for (int o = 16; o > 0; o >>= 1)
            acc += __shfl_xor_sync(0xFFFFFFFFu, acc, o);
        if (tid == 0) s_sum = acc;
    }
    __syncthreads();
    if (tid < KSEL) {
        int idx = (int)(~(unsigned)s_key[tid]);
        out[b * KSEL + tid]             = values[b * L_ + idx];   // values_sel
        out[B_ * KSEL + b * KSEL + tid] = e / s_sum;              // weights
    }
}

// ---------------------------------------------------------------------------
extern "C" void kernel_launch(void* const* d_in, const int* in_sizes, int n_in,
                              void* d_out, int out_size)
{
    const float* q      = (const float*)d_in[0];
    const float* keys   = (const float*)d_in[1];
    const float* values = (const float*)d_in[2];
    const float* g      = (const float*)d_in[3];
    float* out = (float*)d_out;
    (void)in_sizes; (void)n_in; (void)out_size;

    // Tensormap: keys as [32 floats][2L subrows][B], SW128, box {32,256,1}
    typedef CUresult (*EncodeFn)(CUtensorMap*, CUtensorMapDataType, cuuint32_t,
                                 void*, const cuuint64_t*, const cuuint64_t*,
                                 const cuuint32_t*, const cuuint32_t*,
                                 CUtensorMapInterleave, CUtensorMapSwizzle,
                                 CUtensorMapL2promotion, CUtensorMapFloatOOBfill);
    CUtensorMap tmap;
    bool tma_ok = false;
    {
        void* fp = nullptr;
        cudaDriverEntryPointQueryResult qr;
        if (cudaGetDriverEntryPointByVersion("cuTensorMapEncodeTiled", &fp,
                                             12000, cudaEnableDefault, &qr)
                == cudaSuccess && fp) {
            cuuint64_t dims[3]    = {32, (cuuint64_t)2 * L_, B_};
            cuuint64_t strides[2] = {128, (cuuint64_t)L_ * D_ * 4};
            cuuint32_t box[3]     = {32, 2 * TILE, 1};
            cuuint32_t es[3]      = {1, 1, 1};
            EncodeFn fn = (EncodeFn)fp;
            tma_ok = (fn(&tmap, CU_TENSOR_MAP_DATA_TYPE_FLOAT32, 3,
                         (void*)keys, dims, strides, box, es,
                         CU_TENSOR_MAP_INTERLEAVE_NONE,
                         CU_TENSOR_MAP_SWIZZLE_128B,
                         CU_TENSOR_MAP_L2_PROMOTION_L2_128B,
                         CU_TENSOR_MAP_FLOAT_OOB_FILL_NONE) == CUDA_SUCCESS);
        }
    }

    dim3 gridA(L_ / (TILE * NT), B_);
    if (tma_ok) {
        const int smemA = 2 * TILE * D_ * 4 + 256 + 64;   // 65856 B
        cudaFuncSetAttribute(sim_tma_kernel,
                             cudaFuncAttributeMaxDynamicSharedMemorySize, smemA);
        sim_tma_kernel<<<gridA, TILE, smemA>>>(tmap, q, g);
    } else {
        const int smemF = 2 * TILE * ROWW * 4;            // 69632 B
        cudaFuncSetAttribute(sim_kernel,
                             cudaFuncAttributeMaxDynamicSharedMemorySize, smemF);
        sim_kernel<<<gridA, TILE, smemF>>>(q, keys, g);
    }

    topk_kernel<<<B_, 1024>>>(values, out);
}

// round 12
// speedup vs baseline: 1.1763x; 1.1763x over previous
#include <cuda_runtime.h>
#include <cuda.h>
#include <cuda_bf16.h>

#define B_    64
#define L_    16384
#define D_    64
#define KSEL  256
#define TILE  128
#define NT    4
#define ROWW  68
#define CAP   2048
#define TILE_BYTES (TILE * D_ * 4)   // 32768
#define SIM_THR 2.10f                // conservative collect threshold
#define RSHIFT 13                    // refine-histogram granularity (ulps)
#define RNB    1024                  // refine bins
#define N2CAP  768                   // refined candidate cap

__device__ float g_sim[B_ * L_];
__device__ int g_cnt[B_];                        // zero-init; B re-zeroes
__device__ unsigned long long g_cand[B_ * CAP];

__device__ __forceinline__ unsigned f2u(float f) {
    unsigned b = __float_as_uint(f);
    return (b & 0x80000000u) ? ~b : (b | 0x80000000u);
}
__device__ __forceinline__ float u2f(unsigned u) {
    unsigned b = (u & 0x80000000u) ? (u & 0x7FFFFFFFu) : ~u;
    return __uint_as_float(b);
}

// ---- mbarrier / TMA helpers -----------------------------------------------
__device__ __forceinline__ unsigned sm_u32(const void* p) {
    return (unsigned)__cvta_generic_to_shared(p);
}
__device__ __forceinline__ void mbar_init(void* m, unsigned cnt) {
    asm volatile("mbarrier.init.shared.b64 [%0], %1;"
                 :: "r"(sm_u32(m)), "r"(cnt) : "memory");
}
__device__ __forceinline__ void mbar_expect_tx(void* m, unsigned bytes) {
    asm volatile("mbarrier.arrive.expect_tx.shared.b64 _, [%0], %1;"
                 :: "r"(sm_u32(m)), "r"(bytes) : "memory");
}
__device__ __forceinline__ void tma_load3d(void* dst, const CUtensorMap* tm,
                                           int x, int y, int z, void* m) {
    asm volatile(
        "cp.async.bulk.tensor.3d.shared::cta.global.tile.mbarrier::complete_tx::bytes "
        "[%0], [%1, {%2, %3, %4}], [%5];"
        :: "r"(sm_u32(dst)), "l"(tm), "r"(x), "r"(y), "r"(z), "r"(sm_u32(m))
        : "memory");
}
__device__ __forceinline__ void mbar_wait(void* m, unsigned parity) {
    asm volatile(
        "{\n\t.reg .pred P;\n\t"
        "W%=:\n\t"
        "mbarrier.try_wait.parity.acquire.cta.shared::cta.b64 P, [%0], %1, 0x989680;\n\t"
        "@P bra D%=;\n\t"
        "bra W%=;\n\t"
        "D%=:\n\t}"
        :: "r"(sm_u32(m)), "r"(parity) : "memory");
}

// Warp-aggregated append into a SMEM list (ATOMS, no global round trip).
// Caller must invoke from UNIFORM control flow (all 32 lanes).
__device__ __forceinline__ void append_smem(unsigned long long* list, int* cnt,
                                            bool take, unsigned u, int i,
                                            int lane) {
    unsigned m = __ballot_sync(0xFFFFFFFFu, take);
    if (m) {
        int leader = __ffs(m) - 1;
        int basepos = 0;
        if (lane == leader)
            basepos = atomicAdd(cnt, __popc(m));
        basepos = __shfl_sync(0xFFFFFFFFu, basepos, leader);
        if (take)
            list[basepos + __popc(m & ((1u << lane) - 1))] =
                ((unsigned long long)u << 32) | (unsigned)(~i);
    }
}

// refine bin with signed clamp (safe for u below/above the window)
__device__ __forceinline__ unsigned refine_bin(unsigned long long cv,
                                               unsigned ubase) {
    long long sbin = (long long)(unsigned)(cv >> (32 + RSHIFT)) - (long long)ubase;
    if (sbin < 0) sbin = 0;
    if (sbin > RNB - 1) sbin = RNB - 1;
    return (unsigned)sbin;
}

// ---------------------------------------------------------------------------
// Kernel A (TMA + SW128): sims + fused threshold collect (smem-buffered,
// one bulk ATOMG per CTA). FP tree identical to the proven R8 kernel.
// ---------------------------------------------------------------------------
__global__ void __launch_bounds__(TILE) sim_tma_kernel(
    const __grid_constant__ CUtensorMap tmap,
    const float* __restrict__ q,
    const float* __restrict__ gp)
{
    extern __shared__ __align__(1024) float smem[];
    // bytes: [0,65536) bufs | [65536,65792) qsm | [65792,65808) mbar | [65856,+4096) a_cand
    float4* qsm = reinterpret_cast<float4*>(smem + 2 * TILE * D_);
    unsigned long long* mbar =
        reinterpret_cast<unsigned long long*>(smem + 2 * TILE * D_ + 64);
    unsigned long long* a_cand =
        reinterpret_cast<unsigned long long*>(smem + 2 * TILE * D_ + 64 + 16);
    __shared__ int a_n, a_base;

    const int b    = blockIdx.y;
    const int t0   = blockIdx.x * (TILE * NT);
    const int tid  = threadIdx.x;
    const int lane = tid & 31;
    const unsigned uthr = f2u(SIM_THR);

    if (tid < D_ / 4)
        qsm[tid] = reinterpret_cast<const float4*>(q + b * D_)[tid];
    if (tid == 0) { mbar_init(&mbar[0], 1); mbar_init(&mbar[1], 1); a_n = 0; }
    __syncthreads();

    if (tid == 0) {
        mbar_expect_tx(&mbar[0], TILE_BYTES);
        tma_load3d(smem, &tmap, 0, 2 * t0, b, &mbar[0]);
    }

    float qq = 0.f;
#pragma unroll
    for (int i = 0; i < D_ / 4; i++) {
        float4 t = qsm[i];
        qq += t.x * t.x + t.y * t.y + t.z * t.z + t.w * t.w;
    }
    const float rq = gp[0] * rsqrtf(qq);

#pragma unroll
    for (int t = 0; t < NT; t++) {
        if (t + 1 < NT && tid == 0) {
            int nb = (t + 1) & 1;
            mbar_expect_tx(&mbar[nb], TILE_BYTES);
            tma_load3d(smem + nb * (TILE * D_), &tmap,
                       0, 2 * (t0 + (t + 1) * TILE), b, &mbar[nb]);
        }
        mbar_wait(&mbar[t & 1], (t >> 1) & 1);

        const float* base = smem + (t & 1) * (TILE * D_);
        float dot = 0.f, kk = 0.f;
#pragma unroll
        for (int i = 0; i < 16; i++) {
            int r   = 2 * tid + (i >> 3);
            int c16 = (i & 7) ^ (r & 7);
            float4 kv = *reinterpret_cast<const float4*>(base + r * 32 + c16 * 4);
            float4 qv = qsm[i];
            dot += qv.x * kv.x + qv.y * kv.y + qv.z * kv.z + qv.w * kv.w;
            kk  += kv.x * kv.x + kv.y * kv.y + kv.z * kv.z + kv.w * kv.w;
        }
        float sim = dot * rq * rsqrtf(kk);
        int gi = t0 + t * TILE + tid;
        g_sim[b * L_ + gi] = sim;
        unsigned u = f2u(sim);
        append_smem(a_cand, &a_n, u >= uthr, u, gi, lane);   // uniform call

        __syncthreads();   // buffer free before reuse at t+2
    }

    // one bulk global append per CTA
    if (tid == 0 && a_n > 0) a_base = atomicAdd(&g_cnt[b], a_n);
    __syncthreads();
    for (int i = tid; i < a_n; i += TILE) {
        int p = a_base + i;
        if (p < CAP) g_cand[b * CAP + p] = a_cand[i];
    }
}

// ---------------------------------------------------------------------------
// Kernel A fallback (cp.async) — if tensormap encode unavailable.
// ---------------------------------------------------------------------------
__global__ void __launch_bounds__(TILE) sim_kernel(
    const float* __restrict__ q,
    const float* __restrict__ keys,
    const float* __restrict__ gp)
{
    extern __shared__ __align__(16) float tile[];   // [2][TILE*ROWW] + a_cand
    __shared__ __align__(16) float4 qsm[D_ / 4];
    unsigned long long* a_cand =
        reinterpret_cast<unsigned long long*>(tile + 2 * TILE * ROWW);
    __shared__ int a_n, a_base;

    const int b    = blockIdx.y;
    const int t0   = blockIdx.x * (TILE * NT);
    const int tid  = threadIdx.x;
    const int lane = tid & 31;
    const unsigned uthr = f2u(SIM_THR);

    if (tid < D_ / 4)
        qsm[tid] = reinterpret_cast<const float4*>(q + b * D_)[tid];
    if (tid == 0) a_n = 0;

    const float4* kbase = reinterpret_cast<const float4*>(
        keys + (size_t)b * L_ * D_ + (size_t)t0 * D_);

    auto issue = [&](int tt, int buf) {
        const float4* src = kbase + tt * (TILE * 16);
        float* dstbase = tile + buf * (TILE * ROWW);
#pragma unroll
        for (int j = 0; j < 16; j++) {
            int f = j * TILE + tid;
            int l = f >> 4;
            int c = f & 15;
            unsigned dst = sm_u32(&dstbase[l * ROWW + c * 4]);
            asm volatile("cp.async.cg.shared.global [%0], [%1], 16;\n"
                         :: "r"(dst), "l"(src + f));
        }
        asm volatile("cp.async.commit_group;\n");
    };

    issue(0, 0);
    __syncthreads();
    float qq = 0.f;
#pragma unroll
    for (int i = 0; i < D_ / 4; i++) {
        float4 t = qsm[i];
        qq += t.x * t.x + t.y * t.y + t.z * t.z + t.w * t.w;
    }
    const float rq = gp[0] * rsqrtf(qq);

#pragma unroll
    for (int t = 0; t < NT; t++) {
        if (t + 1 < NT) {
            issue(t + 1, (t + 1) & 1);
            asm volatile("cp.async.wait_group 1;\n");
        } else {
            asm volatile("cp.async.wait_group 0;\n");
        }
        __syncthreads();
        const float* tb = tile + (t & 1) * (TILE * ROWW);
        float dot = 0.f, kk = 0.f;
#pragma unroll
        for (int i = 0; i < 16; i++) {
            float4 kv = *reinterpret_cast<const float4*>(&tb[tid * ROWW + i * 4]);
            float4 qv = qsm[i];
            dot += qv.x * kv.x + qv.y * kv.y + qv.z * kv.z + qv.w * kv.w;
            kk  += kv.x * kv.x + kv.y * kv.y + kv.z * kv.z + kv.w * kv.w;
        }
        float sim = dot * rq * rsqrtf(kk);
        int gi = t0 + t * TILE + tid;
        g_sim[b * L_ + gi] = sim;
        unsigned u = f2u(sim);
        append_smem(a_cand, &a_n, u >= uthr, u, gi, lane);   // uniform call
        __syncthreads();
    }

    if (tid == 0 && a_n > 0) a_base = atomicAdd(&g_cnt[b], a_n);
    __syncthreads();
    for (int i = tid; i < a_n; i += TILE) {
        int p = a_base + i;
        if (p < CAP) g_cand[b * CAP + p] = a_cand[i];
    }
}

// ---------------------------------------------------------------------------
// Kernel B: refine (~750 -> ~260) + exact rank + softmax + gather.
// ---------------------------------------------------------------------------
__global__ void __launch_bounds__(1024) topk_kernel(
    const float* __restrict__ values,
    float* __restrict__ out)
{
    __shared__ __align__(16) unsigned long long cand[CAP];    // 16 KB
    __shared__ __align__(16) unsigned long long cand2[N2CAP + 2];
    __shared__ unsigned hist[RNB];                            // 4 KB
    __shared__ int s_rank[CAP];                               // 8 KB
    __shared__ unsigned long long s_key[KSEL];
    __shared__ float s_e[KSEL];
    __shared__ float s_sum;
    __shared__ unsigned s_cnt;
    __shared__ int s_sel, s_n2, s_nin;

    const int b    = blockIdx.x;
    const int tid  = threadIdx.x;
    const int lane = tid & 31;
    const int warp = tid >> 5;
    const int T    = 1024;
    const unsigned ubase = f2u(SIM_THR) >> RSHIFT;

    // race-free count handoff: single reader+resetter, then barrier
    if (tid == 0) { s_nin = g_cnt[b]; g_cnt[b] = 0; }
    __syncthreads();
    int n = s_nin;
    bool ok = (n >= KSEL && n <= CAP - 2);

    if (ok) {
        for (int i = tid; i < n; i += T)
            cand[i] = g_cand[b * CAP + i];
    } else {
        // exact fallback: radix-select the 256th-largest u over g_sim
        const float* simrow = g_sim + b * L_;
        unsigned prefix = 0;
        for (int bit = 31; bit >= 0; bit--) {
            unsigned thr = prefix | (1u << bit);
            if (tid == 0) s_cnt = 0;
            __syncthreads();
            unsigned c = 0;
            for (int i = tid; i < L_; i += T)
                c += (f2u(simrow[i]) >= thr);
            if (c) atomicAdd(&s_cnt, c);
            __syncthreads();
            if (s_cnt >= KSEL) prefix = thr;
            __syncthreads();
        }
        if (tid == 0) s_cnt = 0;
        __syncthreads();
        for (int i = tid; i < L_; i += T) {
            unsigned u = f2u(simrow[i]);
            if (u >= prefix) {
                int p = atomicAdd(&s_cnt, 1);
                if (p < CAP - 2)
                    cand[p] = ((unsigned long long)u << 32) | (unsigned)(~i);
            }
        }
        __syncthreads();
        n = (int)s_cnt;
        if (n > CAP - 2) n = CAP - 2;
    }
    for (int i = tid; i < RNB; i += T) hist[i] = 0;
    if (tid == 0) s_n2 = 0;
    __syncthreads();

    // --- refine histogram over candidates (signed-clamped bins) ---
    for (int i = tid; i < n; i += T)
        atomicAdd(&hist[refine_bin(cand[i], ubase)], 1u);
    __syncthreads();

    // suffix scan (1 bin/thread) -> bin containing rank-256 boundary
    {
        __shared__ unsigned s_wtot[32], s_wabove[32];
        unsigned cnt = hist[tid];
        unsigned suf = cnt;
#pragma unroll
        for (int o = 1; o < 32; o <<= 1) {
            unsigned t = __shfl_down_sync(0xFFFFFFFFu, suf, o);
            if (lane + o < 32) suf += t;
        }
        if (lane == 0) s_wtot[warp] = suf;
        __syncthreads();
        if (warp == 0) {
            unsigned wt = s_wtot[lane];
            unsigned wsuf = wt;
#pragma unroll
            for (int o = 1; o < 32; o <<= 1) {
                unsigned t = __shfl_down_sync(0xFFFFFFFFu, wsuf, o);
                if (lane + o < 32) wsuf += t;
            }
            s_wabove[lane] = wsuf - wt;
        }
        __syncthreads();
        unsigned above = s_wabove[warp] + (suf - cnt);
        if (above < KSEL && above + cnt >= KSEL) s_sel = tid;
        __syncthreads();
    }
    const unsigned selbin = (unsigned)s_sel;

    // compact candidates with bin >= selbin.
    // UNIFORM trip count: every thread runs every iteration (take=false when
    // i >= n) so all 32 lanes reach the ballot — non-uniform exit here was
    // the R10/R11 deadlock.
    for (int i0 = 0; i0 < n; i0 += T) {
        int i = i0 + tid;
        unsigned long long cv = (i < n) ? cand[i] : 0ull;
        bool take = (i < n) && (refine_bin(cv, ubase) >= selbin);
        unsigned m = __ballot_sync(0xFFFFFFFFu, take);
        if (m) {
            int leader = __ffs(m) - 1;
            int basepos = 0;
            if (lane == leader)
                basepos = atomicAdd(&s_n2, __popc(m));
            basepos = __shfl_sync(0xFFFFFFFFu, basepos, leader);
            if (take) {
                int p = basepos + __popc(m & ((1u << lane) - 1));
                if (p < N2CAP) cand2[p] = cv;
            }
        }
    }
    __syncthreads();

    // choose list to rank: refined (typical) or full (pathological overflow)
    unsigned long long* list = cand2;
    int nr = s_n2;
    if (nr > N2CAP) { list = cand; nr = n; }
    if (tid == 0) { list[nr] = 0ull; list[nr + 1] = 0ull; }
    for (int i = tid; i < nr; i += T) s_rank[i] = 0;
    __syncthreads();

    // exact rank (desc value, asc index): quarter-split pairwise count
    {
        const int npairs = (nr + 1) >> 1;
        const int npq    = (npairs + 3) >> 2;
        const int quart  = tid >> 8;
        const int i0     = tid & 255;
        const int jp0    = quart * npq;
        const int jp1    = (jp0 + npq < npairs) ? jp0 + npq : npairs;
        const ulonglong2* cp = reinterpret_cast<const ulonglong2*>(list);

        for (int i = i0; i < nr; i += 256) {
            unsigned long long me = list[i];
            int r = 0;
            for (int jp = jp0; jp < jp1; jp++) {
                ulonglong2 p = cp[jp];
                r += (p.x > me) + (p.y > me);
            }
            if (r) atomicAdd(&s_rank[i], r);
        }
    }
    __syncthreads();

    for (int i = tid; i < nr; i += T) {
        int r = s_rank[i];
        if (r < KSEL) s_key[r] = list[i];
    }
    __syncthreads();

    // softmax over top-256 + gather + output
    float maxs = u2f((unsigned)(s_key[0] >> 32));
    float e = 0.f;
    if (tid < KSEL) {
        e = expf(u2f((unsigned)(s_key[tid] >> 32)) - maxs);
        s_e[tid] = e;
    }
    __syncthreads();
    if (tid < 32) {
        float acc = 0.f;
#pragma unroll
        for (int j = 0; j < KSEL / 32; j++) acc += s_e[tid + j * 32];
#pragma unroll
        for (int o = 16; o > 0; o >>= 1)
            acc += __shfl_xor_sync(0xFFFFFFFFu, acc, o);
        if (tid == 0) s_sum = acc;
    }
    __syncthreads();
    if (tid < KSEL) {
        int idx = (int)(~(unsigned)s_key[tid]);
        out[b * KSEL + tid]             = values[b * L_ + idx];   // values_sel
        out[B_ * KSEL + b * KSEL + tid] = e / s_sum;              // weights
    }
}

// ---------------------------------------------------------------------------
extern "C" void kernel_launch(void* const* d_in, const int* in_sizes, int n_in,
                              void* d_out, int out_size)
{
    const float* q      = (const float*)d_in[0];
    const float* keys   = (const float*)d_in[1];
    const float* values = (const float*)d_in[2];
    const float* g      = (const float*)d_in[3];
    float* out = (float*)d_out;
    (void)in_sizes; (void)n_in; (void)out_size;

    // Tensormap: keys as [32 floats][2L subrows][B], SW128, box {32,256,1}
    typedef CUresult (*EncodeFn)(CUtensorMap*, CUtensorMapDataType, cuuint32_t,
                                 void*, const cuuint64_t*, const cuuint64_t*,
                                 const cuuint32_t*, const cuuint32_t*,
                                 CUtensorMapInterleave, CUtensorMapSwizzle,
                                 CUtensorMapL2promotion, CUtensorMapFloatOOBfill);
    CUtensorMap tmap;
    bool tma_ok = false;
    {
        void* fp = nullptr;
        cudaDriverEntryPointQueryResult qr;
        if (cudaGetDriverEntryPointByVersion("cuTensorMapEncodeTiled", &fp,
                                             12000, cudaEnableDefault, &qr)
                == cudaSuccess && fp) {
            cuuint64_t dims[3]    = {32, (cuuint64_t)2 * L_, B_};
            cuuint64_t strides[2] = {128, (cuuint64_t)L_ * D_ * 4};
            cuuint32_t box[3]     = {32, 2 * TILE, 1};
            cuuint32_t es[3]      = {1, 1, 1};
            EncodeFn fn = (EncodeFn)fp;
            tma_ok = (fn(&tmap, CU_TENSOR_MAP_DATA_TYPE_FLOAT32, 3,
                         (void*)keys, dims, strides, box, es,
                         CU_TENSOR_MAP_INTERLEAVE_NONE,
                         CU_TENSOR_MAP_SWIZZLE_128B,
                         CU_TENSOR_MAP_L2_PROMOTION_L2_128B,
                         CU_TENSOR_MAP_FLOAT_OOB_FILL_NONE) == CUDA_SUCCESS);
        }
    }

    dim3 gridA(L_ / (TILE * NT), B_);
    if (tma_ok) {
        // bufs(65536) + qsm(256) + mbar pad(64) + a_cand(4096) = 69952
        const int smemA = 2 * TILE * D_ * 4 + 256 + 64 + 512 * 8;
        cudaFuncSetAttribute(sim_tma_kernel,
                             cudaFuncAttributeMaxDynamicSharedMemorySize, smemA);
        sim_tma_kernel<<<gridA, TILE, smemA>>>(tmap, q, g);
    } else {
        const int smemF = 2 * TILE * ROWW * 4 + 512 * 8;
        cudaFuncSetAttribute(sim_kernel,
                             cudaFuncAttributeMaxDynamicSharedMemorySize, smemF);
        sim_kernel<<<gridA, TILE, smemF>>>(q, keys, g);
    }

    topk_kernel<<<B_, 1024>>>(values, out);
}